// round 11
// baseline (speedup 1.0000x reference)
// GCRN fused pipeline — R11: revert chain to R9; split edge into pm-only +
// hidden transpose; direct s1/s2 writes (no atomics/zeroing on critical path).
#include <cuda_runtime.h>
#include <cuda_fp16.h>
#include <math.h>
#include <stdint.h>

// Problem constants
#define BB 8
#define NN 1024
#define FF 128
#define GG 64
#define MM 4
#define EE 3
#define BE (BB*EE)        // 24
#define SLOTS (MM*GG)     // 256
#define ROWS (BB*NN)      // 8192
#define HC (MM*EE*GG)     // 768
#define L0C 256
#define L1C 256
#define LOG2E 1.44269504f

// ---------------- scratch ----------------
__device__ __half d_XH [ROWS*FF];
__device__ __half d_WtH[EE*FF*SLOTS];
__device__ __half d_W1H[HC*FF];
__device__ __half d_L0H[FF*L0C];
__device__ __half d_L1H[L0C*L1C];
__device__ __half d_L2H[L1C*FF];
__device__ __half d_Wh [BE*NN*SLOTS];        // [be][n][m*64+g]
__device__ __half d_H  [ROWS*HC];            // [b*N+n][m*192+e*64+g]
__device__ __half d_HnH[ROWS*FF];
__device__ float  d_HnF[ROWS*FF];
__device__ __half d_Z0h[ROWS*L0C];
__device__ __half d_Z1h[ROWS*L1C];
__device__ float  d_s1[BE*MM*NN];            // pre-scaled by log2(e)
__device__ float  d_s2[BE*MM*NN];
__device__ unsigned short d_pm[BE*NN*64];    // bit-packed mask
__device__ float  d_bufA[ROWS*L0C];
__device__ float  d_stats[4*512];

// ---------------- helpers ----------------
__device__ __forceinline__ uint32_t smem_u32(const void* p) {
    return (uint32_t)__cvta_generic_to_shared(p);
}
__device__ __forceinline__ void cp16(uint32_t dst, const void* src) {
    asm volatile("cp.async.cg.shared.global [%0], [%1], 16;" :: "r"(dst), "l"(src) : "memory");
}
#define CP_COMMIT asm volatile("cp.async.commit_group;" ::: "memory")
#define CP_WAIT1  asm volatile("cp.async.wait_group 1;" ::: "memory")
#define CP_WAIT0  asm volatile("cp.async.wait_group 0;" ::: "memory")

__device__ __forceinline__ void ldsm_x4(uint32_t* r, uint32_t addr) {
    asm volatile("ldmatrix.sync.aligned.m8n8.x4.shared.b16 {%0,%1,%2,%3}, [%4];"
        : "=r"(r[0]), "=r"(r[1]), "=r"(r[2]), "=r"(r[3]) : "r"(addr));
}
__device__ __forceinline__ void ldsm_x4t(uint32_t* r, uint32_t addr) {
    asm volatile("ldmatrix.sync.aligned.m8n8.x4.trans.shared.b16 {%0,%1,%2,%3}, [%4];"
        : "=r"(r[0]), "=r"(r[1]), "=r"(r[2]), "=r"(r[3]) : "r"(addr));
}
__device__ __forceinline__ void mma_f16(float* d, const uint32_t* a, uint32_t b0, uint32_t b1) {
    asm volatile(
        "mma.sync.aligned.m16n8k16.row.col.f32.f16.f16.f32 "
        "{%0,%1,%2,%3}, {%4,%5,%6,%7}, {%8,%9}, {%0,%1,%2,%3};"
        : "+f"(d[0]), "+f"(d[1]), "+f"(d[2]), "+f"(d[3])
        : "r"(a[0]), "r"(a[1]), "r"(a[2]), "r"(a[3]), "r"(b0), "r"(b1));
}
__device__ __forceinline__ __half2 ex2_h2(__half2 x) {
    uint32_t xi = *(uint32_t*)&x, r;
    asm("ex2.approx.f16x2 %0, %1;" : "=r"(r) : "r"(xi));
    return *(__half2*)&r;
}

// ---------------- tiny utility kernels ----------------
__global__ void zeroSt_kernel(float4* a) {
    a[threadIdx.x] = make_float4(0.f,0.f,0.f,0.f);   // 512 float4 = 2048 floats
}

__global__ void cvtX_kernel(const float* __restrict__ X) {
    int i4 = blockIdx.x*blockDim.x + threadIdx.x;
    if (i4 >= ROWS*FF/4) return;
    int i = i4*4;
    float4 v = *(const float4*)(X + i);
    *(__half2*)(d_XH + i)     = __floats2half2_rn(v.x, v.y);
    *(__half2*)(d_XH + i + 2) = __floats2half2_rn(v.z, v.w);
}

#define CVT_NW1 (HC*FF)
#define CVT_NL0 (FF*L0C)
#define CVT_NL1 (L0C*L1C)
#define CVT_NL2 (L1C*FF)
#define CVTW_TOT4 ((CVT_NW1+CVT_NL0+CVT_NL1+CVT_NL2)/4)
__global__ void cvtW_kernel(const float* __restrict__ W1, const float* __restrict__ L0,
                            const float* __restrict__ L1, const float* __restrict__ L2) {
    int i4 = blockIdx.x*blockDim.x + threadIdx.x;
    if (i4 >= CVTW_TOT4) return;
    int i = i4*4;
    const float* src; __half* dst;
    if (i < CVT_NW1) { src = W1; dst = d_W1H; }
    else if ((i -= CVT_NW1) < CVT_NL0) { src = L0; dst = d_L0H; }
    else if ((i -= CVT_NL0) < CVT_NL1) { src = L1; dst = d_L1H; }
    else { i -= CVT_NL1; src = L2; dst = d_L2H; }
    float4 v = *(const float4*)(src + i);
    *(__half2*)(dst + i)     = __floats2half2_rn(v.x, v.y);
    *(__half2*)(dst + i + 2) = __floats2half2_rn(v.z, v.w);
}

__global__ void wt_kernel(const float* __restrict__ Ws) {
    int idx = blockIdx.x*blockDim.x + threadIdx.x;
    if (idx >= EE*FF*SLOTS) return;
    int e = idx >> 15;
    int r = idx & 32767;
    int f = r >> 8;
    int c = r & 255;
    int m = c >> 6, g = c & 63;
    d_WtH[idx] = __float2half(Ws[e*32768 + m*8192 + f*64 + g]);
}

// pm-only: warp per (be,i) row; ballot per 32-j chunk. Minimal critical-path latency.
__global__ void __launch_bounds__(256) pm2_kernel(
        const int* __restrict__ A, unsigned short* __restrict__ pm) {
    int bei = blockIdx.x*8 + (threadIdx.x >> 5);   // be*1024 + i
    int lane = threadIdx.x & 31;
    const int* src = A + (long)bei*1024;
    uint32_t* pmW = (uint32_t*)pm + (long)bei*32;
#pragma unroll 4
    for (int jw = 0; jw < 32; jw++) {
        int a = __ldcs(src + jw*32 + lane);
        unsigned bal = __ballot_sync(0xffffffffu, a > 0);
        if (lane == 0) pmW[jw] = bal;
    }
}

// edge_cat transpose only (runs hidden on side stream)
__global__ void __launch_bounds__(256) edgecat_kernel(
        const int* __restrict__ A, float* __restrict__ out) {
    __shared__ float sv[3072];
    int bi = blockIdx.x;
    int b = bi >> 10, i = bi & 1023;
    int t = threadIdx.x;
#pragma unroll
    for (int e = 0; e < 3; e++) {
        const int* src = A + (((long)(b*3+e) << 10) + i)*1024;
#pragma unroll
        for (int k = 0; k < 4; k++) {
            int j = t + k*256;
            sv[j*3 + e] = (float)__ldcs(src + j);
        }
    }
    __syncthreads();
    float4* o = (float4*)(out + (long)bi*3072);
    const float4* s4 = (const float4*)sv;
#pragma unroll
    for (int k = 0; k < 3; k++) __stcs(o + t + k*256, s4[t + k*256]);
}

// ---------------- gemm4: fp16 x fp16 -> fp32, cp.async 2-stage pipeline ----------------
// 64x64 tile, k-tile 32, 8 warps each 16m x 32n. Optional residual/stats fusion;
// projection variant writes s1/s2 directly (block owns its rows exclusively).
#define AS_H 40
#define BS_H 72
template <int CH>
__global__ void __launch_bounds__(256) gemm4_kernel(
        const __half* __restrict__ Ah, const __half* __restrict__ Bh, void* __restrict__ Cout,
        int M, int N, int K,
        long sA, long sB, long sC, int zDivA, int zModB,
        float alpha, const float* __restrict__ R, float beta,
        float* __restrict__ stats,
        const float* __restrict__ a1, const float* __restrict__ a2,
        float* __restrict__ s1o, float* __restrict__ s2o) {
    __shared__ __half As[2][64*AS_H];
    __shared__ __half Bs[2][32*BS_H];
    __shared__ float sRed[4][16][2][2];   // [mg][row16][s1|s2][ncol-half]
    int z = blockIdx.z;
    Ah += (long)(z / zDivA) * sA;
    Bh += (long)(z % zModB) * sB;
    float*  Cf = (float*)Cout + (CH ? 0 : (long)z * sC);
    __half* Ch = (__half*)Cout + (CH ? (long)z * sC : 0);

    int n0 = blockIdx.x * 64, m0 = blockIdx.y * 64;
    int t = threadIdx.x, lane = t & 31, w = t >> 5;
    int gid = lane >> 2, tig = lane & 3;
    int mrow = (w & 3) * 16, ncol = (w >> 2) * 32;
    int l16 = lane & 15, lhi = (lane >> 4) * 8;

    int am_ = t >> 2, akq = (t & 3) * 8;
    int bkk = t >> 3, bnq = (t & 7) * 8;
    long aoff = (long)(m0 + am_)*K + akq;
    long boff = (long)bkk*N + n0 + bnq;
    uint32_t adst[2] = { smem_u32(&As[0][am_*AS_H + akq]), smem_u32(&As[1][am_*AS_H + akq]) };
    uint32_t bdst[2] = { smem_u32(&Bs[0][bkk*BS_H + bnq]), smem_u32(&Bs[1][bkk*BS_H + bnq]) };
    uint32_t aA[2] = { smem_u32(&As[0][(mrow+l16)*AS_H + lhi]), smem_u32(&As[1][(mrow+l16)*AS_H + lhi]) };
    uint32_t aB[2] = { smem_u32(&Bs[0][l16*BS_H + ncol + lhi]), smem_u32(&Bs[1][l16*BS_H + ncol + lhi]) };

    float acc[4][4];
#pragma unroll
    for (int nt = 0; nt < 4; nt++)
#pragma unroll
        for (int q = 0; q < 4; q++) acc[nt][q] = 0.f;

    int T = K >> 5;
    cp16(adst[0], Ah + aoff);
    cp16(bdst[0], Bh + boff);
    CP_COMMIT;

    for (int tk = 0; tk < T; tk++) {
        int st = tk & 1;
        __syncthreads();
        if (tk+1 < T) {
            int k0 = (tk+1) << 5;
            cp16(adst[st^1], Ah + aoff + k0);
            cp16(bdst[st^1], Bh + boff + (long)k0*N);
            CP_COMMIT;
            CP_WAIT1;
        } else {
            CP_WAIT0;
        }
        __syncthreads();
#pragma unroll
        for (int ks = 0; ks < 2; ks++) {
            uint32_t af[4];
            ldsm_x4(af, aA[st] + ks*32);
            uint32_t bfr[2][4];
#pragma unroll
            for (int ntp = 0; ntp < 2; ntp++)
                ldsm_x4t(bfr[ntp], aB[st] + (ks*16*BS_H + ntp*16)*2);
#pragma unroll
            for (int nt = 0; nt < 4; nt++)
                mma_f16(acc[nt], af, bfr[nt>>1][(nt&1)*2], bfr[nt>>1][(nt&1)*2+1]);
        }
    }
    // epilogue (fragment layout)
    float stS[4][2], stQ[4][2];
    float d1a = 0.f, d1b = 0.f, d2a = 0.f, d2b = 0.f;
    const float* a1e = a1 ? a1 + (z % 3)*SLOTS : nullptr;
    const float* a2e = a2 ? a2 + (z % 3)*SLOTS : nullptr;
    long r0 = m0 + mrow + gid, r1 = r0 + 8;
#pragma unroll
    for (int nt = 0; nt < 4; nt++) {
        int c = n0 + ncol + nt*8 + 2*tig;
        float v0 = alpha*acc[nt][0], v1 = alpha*acc[nt][1];
        float v2 = alpha*acc[nt][2], v3 = alpha*acc[nt][3];
        if (R) {
            float2 ra = *(const float2*)(R + r0*N + c);
            float2 rb = *(const float2*)(R + r1*N + c);
            v0 += beta*ra.x; v1 += beta*ra.y; v2 += beta*rb.x; v3 += beta*rb.y;
        }
        if (CH) {
            *(__half2*)(Ch + r0*N + c) = __floats2half2_rn(v0, v1);
            *(__half2*)(Ch + r1*N + c) = __floats2half2_rn(v2, v3);
        } else {
            *(float2*)(Cf + r0*N + c) = make_float2(v0, v1);
            *(float2*)(Cf + r1*N + c) = make_float2(v2, v3);
        }
        if (a1e) {
            float w10 = a1e[c]*LOG2E, w11 = a1e[c+1]*LOG2E;
            float w20 = a2e[c]*LOG2E, w21 = a2e[c+1]*LOG2E;
            d1a += v0*w10 + v1*w11; d1b += v2*w10 + v3*w11;
            d2a += v0*w20 + v1*w21; d2b += v2*w20 + v3*w21;
        }
        stS[nt][0] = v0 + v2; stS[nt][1] = v1 + v3;
        stQ[nt][0] = v0*v0 + v2*v2; stQ[nt][1] = v1*v1 + v3*v3;
    }
    if (a1) {
        // direct s1/s2: block (head = n0>>6) owns rows m0..m0+63 exclusively
        d1a += __shfl_down_sync(0xffffffffu, d1a, 1); d1a += __shfl_down_sync(0xffffffffu, d1a, 2);
        d1b += __shfl_down_sync(0xffffffffu, d1b, 1); d1b += __shfl_down_sync(0xffffffffu, d1b, 2);
        d2a += __shfl_down_sync(0xffffffffu, d2a, 1); d2a += __shfl_down_sync(0xffffffffu, d2a, 2);
        d2b += __shfl_down_sync(0xffffffffu, d2b, 1); d2b += __shfl_down_sync(0xffffffffu, d2b, 2);
        int mg = w & 3, half = w >> 2;
        if (tig == 0) {
            sRed[mg][gid][0][half]     = d1a;
            sRed[mg][gid+8][0][half]   = d1b;
            sRed[mg][gid][1][half]     = d2a;
            sRed[mg][gid+8][1][half]   = d2b;
        }
        __syncthreads();
        if (t < 128) {
            int tmg = t >> 5, rem = t & 31, row16 = rem & 15, which = rem >> 4;
            float v = sRed[tmg][row16][which][0] + sRed[tmg][row16][which][1];
            int mhead = n0 >> 6;
            long row = m0 + tmg*16 + row16;
            float* dst = (which ? s2o : s1o) + (z*4 + mhead)*NN + row;
            *dst = v;
        }
    }
    if (stats) {
#pragma unroll
        for (int nt = 0; nt < 4; nt++) {
#pragma unroll
            for (int cc = 0; cc < 2; cc++) {
                float s = stS[nt][cc], q = stQ[nt][cc];
#pragma unroll
                for (int off = 16; off >= 4; off >>= 1) {
                    s += __shfl_down_sync(0xffffffffu, s, off);
                    q += __shfl_down_sync(0xffffffffu, q, off);
                }
                if (lane < 4) {
                    int col = n0 + ncol + nt*8 + 2*lane + cc;
                    atomicAdd(&stats[col], s);
                    atomicAdd(&stats[N + col], q);
                }
            }
        }
    }
}

// ---------------- attention v5: half2 softmax (ex2.f16x2) + packed mask ----------------
#define SWH_H 264
#define SP_H  40
__global__ void __launch_bounds__(256, 3) att5_kernel(
        const unsigned short* __restrict__ pm, const __half* __restrict__ Wh,
        const float* __restrict__ s1, const float* __restrict__ s2,
        __half* __restrict__ H) {
    __shared__ __half sWh[2][32*SWH_H];
    __shared__ __half sP[4*32*SP_H];
    __shared__ float sDen[1024];
    __shared__ float sDen2[128];

    const int be = blockIdx.y;
    const int b  = be / 3, e = be % 3;
    const int i0 = blockIdx.x * 32;
    const int t  = threadIdx.x;
    const int lane = t & 31;
    const int w  = t >> 5;
    const int gid = lane >> 2, tig = lane & 3;
    const int l16 = lane & 15, lhi = (lane >> 4) * 8;

    const int ip = t >> 3;
    const int jg = t & 7;
    const int am = w >> 1;
    const int nh = (w & 1) * 32;

    const __half2 c001 = __float2half2_rn(0.01f);

    float s1v[4];
#pragma unroll
    for (int m = 0; m < 4; m++) s1v[m] = s1[(be*4+m)*NN + i0 + ip];

    float den[4] = {0.f,0.f,0.f,0.f};
    float acc[2][4][4];
#pragma unroll
    for (int mt = 0; mt < 2; mt++)
#pragma unroll
        for (int nt = 0; nt < 4; nt++)
#pragma unroll
            for (int q = 0; q < 4; q++) acc[mt][nt][q] = 0.f;

    const uint32_t* pmRow = (const uint32_t*)pm + ((long)be*NN + i0 + ip)*32;
    const __half* WhB = Wh + (long)be*NN*SLOTS;
    const float* s2b  = s2 + be*4*NN;

    int off[4];
    uint32_t wdst[2][4];
#pragma unroll
    for (int k = 0; k < 4; k++) {
        int idx = t + k*256;
        int jj = idx >> 5, cq = idx & 31;
        off[k] = jj*256 + cq*8;
        wdst[0][k] = smem_u32(&sWh[0][jj*SWH_H + cq*8]);
        wdst[1][k] = smem_u32(&sWh[1][jj*SWH_H + cq*8]);
    }
    uint32_t aP = smem_u32(&sP[(am*32 + l16)*SP_H + lhi]);
    uint32_t aW[2] = { smem_u32(&sWh[0][l16*SWH_H + am*64 + nh + lhi]),
                       smem_u32(&sWh[1][l16*SWH_H + am*64 + nh + lhi]) };

#pragma unroll
    for (int k = 0; k < 4; k++) cp16(wdst[0][k], WhB + off[k]);
    CP_COMMIT;

    for (int jt = 0; jt < 32; jt++) {
        const int j0 = jt << 5;
        const int st = jt & 1;
        __syncthreads();
        if (jt+1 < 32) {
            const __half* src = WhB + (long)(j0+32)*SLOTS;
#pragma unroll
            for (int k = 0; k < 4; k++) cp16(wdst[st^1][k], src + off[k]);
            CP_COMMIT;
        }
        {
            uint32_t nib = pmRow[jt] >> (jg*4);
            __half2 hm01 = __floats2half2_rn((float)(nib & 1u), (float)((nib >> 1) & 1u));
            __half2 hm23 = __floats2half2_rn((float)((nib >> 2) & 1u), (float)((nib >> 3) & 1u));
#pragma unroll
            for (int m = 0; m < 4; m++) {
                float4 s4 = *(const float4*)(s2b + m*NN + j0 + jg*4);
                __half2 x01 = __floats2half2_rn(s1v[m]+s4.x, s1v[m]+s4.y);
                __half2 x23 = __floats2half2_rn(s1v[m]+s4.z, s1v[m]+s4.w);
                x01 = __hmax2(x01, __hmul2(x01, c001));
                x23 = __hmax2(x23, __hmul2(x23, c001));
                __half2 p01 = __hmul2(ex2_h2(x01), hm01);
                __half2 p23 = __hmul2(ex2_h2(x23), hm23);
                __half2 hp[2] = {p01, p23};
                *(uint2*)&sP[(m*32 + ip)*SP_H + jg*4] = *(uint2*)hp;
                float2 df = __half22float2(__hadd2(p01, p23));
                den[m] += df.x + df.y;
            }
        }
        if (jt+1 < 32) { CP_WAIT1; } else { CP_WAIT0; }
        __syncthreads();
#pragma unroll
        for (int ks = 0; ks < 2; ks++) {
            uint32_t bfr[2][4];
#pragma unroll
            for (int ntp = 0; ntp < 2; ntp++)
                ldsm_x4t(bfr[ntp], aW[st] + (ks*16*SWH_H + ntp*16)*2);
#pragma unroll
            for (int mt = 0; mt < 2; mt++) {
                uint32_t af[4];
                ldsm_x4(af, aP + (mt*16*SP_H + ks*16)*2);
#pragma unroll
                for (int nt = 0; nt < 4; nt++)
                    mma_f16(acc[mt][nt], af, bfr[nt>>1][(nt&1)*2], bfr[nt>>1][(nt&1)*2+1]);
            }
        }
    }
    __syncthreads();
#pragma unroll
    for (int m = 0; m < 4; m++) sDen[(m*32 + ip)*8 + jg] = den[m];
    __syncthreads();
    if (t < 128) {
        float s = 0.f;
#pragma unroll
        for (int r = 0; r < 8; r++) s += sDen[t*8 + r];
        sDen2[t] = 1.f / fmaxf(s, 1e-30f);
    }
    __syncthreads();
#pragma unroll
    for (int mt = 0; mt < 2; mt++) {
        int r0 = mt*16 + gid;
        float inv0 = sDen2[am*32 + r0];
        float inv1 = sDen2[am*32 + r0 + 8];
        long row0 = (long)(b*NN) + i0 + r0;
        long row1 = row0 + 8;
#pragma unroll
        for (int nt = 0; nt < 4; nt++) {
            int col = am*192 + e*64 + nh + nt*8 + 2*tig;
            float v0 = acc[mt][nt][0]*inv0, v1 = acc[mt][nt][1]*inv0;
            float v2 = acc[mt][nt][2]*inv1, v3 = acc[mt][nt][3]*inv1;
            v0 = (v0 > 0.f) ? v0 : expm1f(v0);
            v1 = (v1 > 0.f) ? v1 : expm1f(v1);
            v2 = (v2 > 0.f) ? v2 : expm1f(v2);
            v3 = (v3 > 0.f) ? v3 : expm1f(v3);
            *(__half2*)(H + row0*HC + col) = __floats2half2_rn(v0, v1);
            *(__half2*)(H + row1*HC + col) = __floats2half2_rn(v2, v3);
        }
    }
}

// ---------------- batchnorm normalize: fp32 in -> fp16 (+opt fp32) out ----------------
__global__ void norm2_kernel(const float* __restrict__ Y, __half* __restrict__ oh,
                             float* __restrict__ of,
                             const float* __restrict__ stats,
                             const float* __restrict__ g, const float* __restrict__ bb,
                             int N, int elu) {
    int i4 = blockIdx.x*blockDim.x + threadIdx.x;
    if (i4 >= ROWS*N/4) return;
    int i = i4*4;
    int col = i & (N - 1);
    const float invM = 1.f / (float)ROWS;
    float4 y = *(const float4*)(Y + i);
    float4 sm = *(const float4*)(stats + col);
    float4 sq = *(const float4*)(stats + N + col);
    float4 gg = *(const float4*)(g + col);
    float4 bv = *(const float4*)(bb + col);
    float m0 = sm.x*invM, m1 = sm.y*invM, m2 = sm.z*invM, m3 = sm.w*invM;
    float w0 = gg.x * rsqrtf(sq.x*invM - m0*m0 + 1e-5f);
    float w1 = gg.y * rsqrtf(sq.y*invM - m1*m1 + 1e-5f);
    float w2 = gg.z * rsqrtf(sq.z*invM - m2*m2 + 1e-5f);
    float w3 = gg.w * rsqrtf(sq.w*invM - m3*m3 + 1e-5f);
    float v0 = (y.x - m0)*w0 + bv.x;
    float v1 = (y.y - m1)*w1 + bv.y;
    float v2 = (y.z - m2)*w2 + bv.z;
    float v3 = (y.w - m3)*w3 + bv.w;
    if (elu) {
        v0 = (v0 > 0.f) ? v0 : expm1f(v0);
        v1 = (v1 > 0.f) ? v1 : expm1f(v1);
        v2 = (v2 > 0.f) ? v2 : expm1f(v2);
        v3 = (v3 > 0.f) ? v3 : expm1f(v3);
    }
    if (oh) {
        *(__half2*)(oh + i)     = __floats2half2_rn(v0, v1);
        *(__half2*)(oh + i + 2) = __floats2half2_rn(v2, v3);
    }
    if (of) *(float4*)(of + i) = make_float4(v0, v1, v2, v3);
}

// ---------------- launch ----------------
extern "C" void kernel_launch(void* const* d_in, const int* in_sizes, int n_in,
                              void* d_out, int out_size) {
    const int*   A      = (const int*)  d_in[0];
    const float* X      = (const float*)d_in[1];
    const float* Ws     = (const float*)d_in[3];
    const float* a1     = (const float*)d_in[4];
    const float* a2     = (const float*)d_in[5];
    const float* W1     = (const float*)d_in[6];
    const float* bn1_g  = (const float*)d_in[7];
    const float* bn1_b  = (const float*)d_in[8];
    const float* e_l0   = (const float*)d_in[9];
    const float* e_bn0g = (const float*)d_in[10];
    const float* e_bn0b = (const float*)d_in[11];
    const float* e_l1   = (const float*)d_in[12];
    const float* e_bn1g = (const float*)d_in[13];
    const float* e_bn1b = (const float*)d_in[14];
    const float* e_l2   = (const float*)d_in[15];
    const float* bn2_g  = (const float*)d_in[16];
    const float* bn2_b  = (const float*)d_in[17];
    float* out = (float*)d_out;

    float *ps1, *ps2, *pHnF, *pA, *pSt;
    __half *pXH, *pWtH, *pW1H, *pL0H, *pL1H, *pL2H, *pWh, *pH, *pHnH, *pZ0, *pZ1;
    unsigned short* ppm;
    cudaGetSymbolAddress((void**)&pXH,  d_XH);
    cudaGetSymbolAddress((void**)&pWtH, d_WtH);
    cudaGetSymbolAddress((void**)&pW1H, d_W1H);
    cudaGetSymbolAddress((void**)&pL0H, d_L0H);
    cudaGetSymbolAddress((void**)&pL1H, d_L1H);
    cudaGetSymbolAddress((void**)&pL2H, d_L2H);
    cudaGetSymbolAddress((void**)&pWh,  d_Wh);
    cudaGetSymbolAddress((void**)&pH,   d_H);
    cudaGetSymbolAddress((void**)&pHnH, d_HnH);
    cudaGetSymbolAddress((void**)&pHnF, d_HnF);
    cudaGetSymbolAddress((void**)&pZ0,  d_Z0h);
    cudaGetSymbolAddress((void**)&pZ1,  d_Z1h);
    cudaGetSymbolAddress((void**)&ps1,  d_s1);
    cudaGetSymbolAddress((void**)&ps2,  d_s2);
    cudaGetSymbolAddress((void**)&ppm,  d_pm);
    cudaGetSymbolAddress((void**)&pA,   d_bufA);
    cudaGetSymbolAddress((void**)&pSt,  d_stats);

    static cudaStream_t s2str = nullptr;
    static cudaEvent_t evFork = nullptr, evPm = nullptr, evW = nullptr, evCat = nullptr;
    if (!s2str) {
        cudaStreamCreateWithFlags(&s2str, cudaStreamNonBlocking);
        cudaEventCreateWithFlags(&evFork, cudaEventDisableTiming);
        cudaEventCreateWithFlags(&evPm,   cudaEventDisableTiming);
        cudaEventCreateWithFlags(&evW,    cudaEventDisableTiming);
        cudaEventCreateWithFlags(&evCat,  cudaEventDisableTiming);
    }

    // Side stream: pm (needed by att) -> weights + stats-zero (needed by chain)
    // -> edge_cat transpose (needed only at graph end, fully hidden)
    cudaEventRecord(evFork, 0);
    cudaStreamWaitEvent(s2str, evFork, 0);
    pm2_kernel<<<BE*NN/8, 256, 0, s2str>>>(A, ppm);
    cudaEventRecord(evPm, s2str);
    cvtW_kernel<<<(CVTW_TOT4+255)/256, 256, 0, s2str>>>(W1, e_l0, e_l1, e_l2);
    zeroSt_kernel<<<1, 512, 0, s2str>>>((float4*)pSt);
    cudaEventRecord(evW, s2str);
    edgecat_kernel<<<ROWS, 256, 0, s2str>>>(A, out + ROWS*FF);
    cudaEventRecord(evCat, s2str);

    // Main prologue
    cvtX_kernel<<<(ROWS*FF/4+255)/256, 256>>>(X);
    wt_kernel<<<384, 256>>>(Ws);

    // Wh projection + direct s1/s2 (log2e-scaled)
    gemm4_kernel<1><<<dim3(SLOTS/64, NN/64, BE), 256>>>(
        pXH, pWtH, pWh, NN, SLOTS, FF,
        (long)NN*FF, (long)FF*SLOTS, (long)NN*SLOTS, EE, EE,
        1.f, nullptr, 0.f, nullptr, a1, a2, ps1, ps2);

    cudaStreamWaitEvent(0, evPm, 0);

    // fused masked softmax + P@Wh + ELU -> H
    att5_kernel<<<dim3(NN/32, BE), 256>>>(ppm, pWh, ps1, ps2, pH);

    cudaStreamWaitEvent(0, evW, 0);

    // H @ W1 * 0.5 + 0.5*X -> bufA, stats0; bn1 -> HnH + HnF
    gemm4_kernel<0><<<dim3(FF/64, ROWS/64, 1), 256>>>(
        pH, pW1H, pA, ROWS, FF, HC, 0,0,0, 1,1,
        0.5f, X, 0.5f, pSt + 0, nullptr, nullptr, nullptr, nullptr);
    norm2_kernel<<<(ROWS*FF/4+255)/256, 256>>>(pA, pHnH, pHnF, pSt + 0, bn1_g, bn1_b, FF, 0);

    // Hn @ e_l0 -> bufA, stats1; elu(bn) -> Z0
    gemm4_kernel<0><<<dim3(L0C/64, ROWS/64, 1), 256>>>(
        pHnH, pL0H, pA, ROWS, L0C, FF, 0,0,0, 1,1,
        1.f, nullptr, 0.f, pSt + 512, nullptr, nullptr, nullptr, nullptr);
    norm2_kernel<<<(ROWS*L0C/4+255)/256, 256>>>(pA, pZ0, nullptr, pSt + 512, e_bn0g, e_bn0b, L0C, 1);

    // Z0 @ e_l1 -> bufA, stats2; elu(bn) -> Z1
    gemm4_kernel<0><<<dim3(L1C/64, ROWS/64, 1), 256>>>(
        pZ0, pL1H, pA, ROWS, L1C, L0C, 0,0,0, 1,1,
        1.f, nullptr, 0.f, pSt + 1024, nullptr, nullptr, nullptr, nullptr);
    norm2_kernel<<<(ROWS*L1C/4+255)/256, 256>>>(pA, pZ1, nullptr, pSt + 1024, e_bn1g, e_bn1b, L1C, 1);

    // Z1 @ e_l2 + HnF -> bufA, stats3; bn2 -> out
    gemm4_kernel<0><<<dim3(FF/64, ROWS/64, 1), 256>>>(
        pZ1, pL2H, pA, ROWS, FF, L1C, 0,0,0, 1,1,
        1.f, pHnF, 1.f, pSt + 1536, nullptr, nullptr, nullptr, nullptr);

    cudaStreamWaitEvent(0, evCat, 0);   // join side stream before final kernel

    norm2_kernel<<<(ROWS*FF/4+255)/256, 256>>>(pA, nullptr, out, pSt + 1536, bn2_g, bn2_b, FF, 0);
}

// round 12
// speedup vs baseline: 1.0921x; 1.0921x over previous
// GCRN fused pipeline — R12: R9 topology (edge2 joined before att) +
// direct s1/s2 stores + single prep kernel (cvt+wt+zero merged).
#include <cuda_runtime.h>
#include <cuda_fp16.h>
#include <math.h>
#include <stdint.h>

// Problem constants
#define BB 8
#define NN 1024
#define FF 128
#define GG 64
#define MM 4
#define EE 3
#define BE (BB*EE)        // 24
#define SLOTS (MM*GG)     // 256
#define ROWS (BB*NN)      // 8192
#define HC (MM*EE*GG)     // 768
#define L0C 256
#define L1C 256
#define LOG2E 1.44269504f

// ---------------- scratch ----------------
__device__ __half d_XH [ROWS*FF];
__device__ __half d_WtH[EE*FF*SLOTS];
__device__ __half d_W1H[HC*FF];
__device__ __half d_L0H[FF*L0C];
__device__ __half d_L1H[L0C*L1C];
__device__ __half d_L2H[L1C*FF];
__device__ __half d_Wh [BE*NN*SLOTS];        // [be][n][m*64+g]
__device__ __half d_H  [ROWS*HC];            // [b*N+n][m*192+e*64+g]
__device__ __half d_HnH[ROWS*FF];
__device__ float  d_HnF[ROWS*FF];
__device__ __half d_Z0h[ROWS*L0C];
__device__ __half d_Z1h[ROWS*L1C];
__device__ float  d_s1[BE*MM*NN];            // pre-scaled by log2(e)
__device__ float  d_s2[BE*MM*NN];
__device__ unsigned short d_pm[BE*NN*64];    // bit-packed mask
__device__ float  d_bufA[ROWS*L0C];
__device__ float  d_stats[4*512];

// ---------------- helpers ----------------
__device__ __forceinline__ uint32_t smem_u32(const void* p) {
    return (uint32_t)__cvta_generic_to_shared(p);
}
__device__ __forceinline__ void cp16(uint32_t dst, const void* src) {
    asm volatile("cp.async.cg.shared.global [%0], [%1], 16;" :: "r"(dst), "l"(src) : "memory");
}
#define CP_COMMIT asm volatile("cp.async.commit_group;" ::: "memory")
#define CP_WAIT1  asm volatile("cp.async.wait_group 1;" ::: "memory")
#define CP_WAIT0  asm volatile("cp.async.wait_group 0;" ::: "memory")

__device__ __forceinline__ void ldsm_x4(uint32_t* r, uint32_t addr) {
    asm volatile("ldmatrix.sync.aligned.m8n8.x4.shared.b16 {%0,%1,%2,%3}, [%4];"
        : "=r"(r[0]), "=r"(r[1]), "=r"(r[2]), "=r"(r[3]) : "r"(addr));
}
__device__ __forceinline__ void ldsm_x4t(uint32_t* r, uint32_t addr) {
    asm volatile("ldmatrix.sync.aligned.m8n8.x4.trans.shared.b16 {%0,%1,%2,%3}, [%4];"
        : "=r"(r[0]), "=r"(r[1]), "=r"(r[2]), "=r"(r[3]) : "r"(addr));
}
__device__ __forceinline__ void mma_f16(float* d, const uint32_t* a, uint32_t b0, uint32_t b1) {
    asm volatile(
        "mma.sync.aligned.m16n8k16.row.col.f32.f16.f16.f32 "
        "{%0,%1,%2,%3}, {%4,%5,%6,%7}, {%8,%9}, {%0,%1,%2,%3};"
        : "+f"(d[0]), "+f"(d[1]), "+f"(d[2]), "+f"(d[3])
        : "r"(a[0]), "r"(a[1]), "r"(a[2]), "r"(a[3]), "r"(b0), "r"(b1));
}
__device__ __forceinline__ __half2 ex2_h2(__half2 x) {
    uint32_t xi = *(uint32_t*)&x, r;
    asm("ex2.approx.f16x2 %0, %1;" : "=r"(r) : "r"(xi));
    return *(__half2*)&r;
}

// ---------------- prep: cvt(X,W1,L0,L1,L2) + Ws relayout + stats zero, one launch ----
#define CVT_NX (ROWS*FF)
#define CVT_NW1 (HC*FF)
#define CVT_NL0 (FF*L0C)
#define CVT_NL1 (L0C*L1C)
#define CVT_NL2 (L1C*FF)
#define CVT_TOT4 ((CVT_NX+CVT_NW1+CVT_NL0+CVT_NL1+CVT_NL2)/4)
#define CVT_BLOCKS ((CVT_TOT4+255)/256)
#define WT_BLOCKS 384
#define PREP_BLOCKS (CVT_BLOCKS + WT_BLOCKS + 2)
__global__ void prep_kernel(const float* __restrict__ X, const float* __restrict__ W1,
                            const float* __restrict__ L0, const float* __restrict__ L1,
                            const float* __restrict__ L2, const float* __restrict__ Ws,
                            float4* __restrict__ stats) {
    int bx = blockIdx.x;
    if (bx < CVT_BLOCKS) {
        int i4 = bx*256 + threadIdx.x;
        if (i4 >= CVT_TOT4) return;
        int i = i4*4;
        const float* src; __half* dst;
        if (i < CVT_NX) { src = X; dst = d_XH; }
        else if ((i -= CVT_NX) < CVT_NW1) { src = W1; dst = d_W1H; }
        else if ((i -= CVT_NW1) < CVT_NL0) { src = L0; dst = d_L0H; }
        else if ((i -= CVT_NL0) < CVT_NL1) { src = L1; dst = d_L1H; }
        else { i -= CVT_NL1; src = L2; dst = d_L2H; }
        float4 v = *(const float4*)(src + i);
        *(__half2*)(dst + i)     = __floats2half2_rn(v.x, v.y);
        *(__half2*)(dst + i + 2) = __floats2half2_rn(v.z, v.w);
    } else if (bx < CVT_BLOCKS + WT_BLOCKS) {
        int idx = (bx - CVT_BLOCKS)*256 + threadIdx.x;
        int e = idx >> 15;
        int r = idx & 32767;
        int f = r >> 8;
        int c = r & 255;
        int m = c >> 6, g = c & 63;
        d_WtH[idx] = __float2half(Ws[e*32768 + m*8192 + f*64 + g]);
    } else {
        int i = (bx - CVT_BLOCKS - WT_BLOCKS)*256 + threadIdx.x;
        if (i < 512) stats[i] = make_float4(0.f,0.f,0.f,0.f);
    }
}

// edge v2 (R9): smem transpose for coalesced stores + ballot mask, single A read
__global__ void __launch_bounds__(256) edge2_kernel(
        const int* __restrict__ A, float* __restrict__ out,
        unsigned short* __restrict__ pm) {
    __shared__ float sv[3072];
    int bi = blockIdx.x;
    int b = bi >> 10, i = bi & 1023;
    int t = threadIdx.x;
    int lane = t & 31, w = t >> 5;
#pragma unroll
    for (int e = 0; e < 3; e++) {
        const int* src = A + (((long)(b*3+e) << 10) + i)*1024;
        uint32_t* pmW = (uint32_t*)pm + (((long)(b*3+e) << 10) + i)*32;
#pragma unroll
        for (int k = 0; k < 4; k++) {
            int j = t + k*256;
            int a = __ldcs(src + j);
            sv[j*3 + e] = (float)a;
            unsigned bal = __ballot_sync(0xffffffffu, a > 0);
            if (lane == 0) pmW[k*8 + w] = bal;
        }
    }
    __syncthreads();
    float4* o = (float4*)(out + (long)bi*3072);
    const float4* s4 = (const float4*)sv;
#pragma unroll
    for (int k = 0; k < 3; k++) __stcs(o + t + k*256, s4[t + k*256]);
}

// ---------------- gemm4: fp16 x fp16 -> fp32, cp.async 2-stage pipeline ----------------
// 64x64 tile, k-tile 32, 8 warps each 16m x 32n. Residual/stats fusion; projection
// variant writes s1/s2 directly (block owns its rows exclusively).
#define AS_H 40
#define BS_H 72
template <int CH>
__global__ void __launch_bounds__(256) gemm4_kernel(
        const __half* __restrict__ Ah, const __half* __restrict__ Bh, void* __restrict__ Cout,
        int M, int N, int K,
        long sA, long sB, long sC, int zDivA, int zModB,
        float alpha, const float* __restrict__ R, float beta,
        float* __restrict__ stats,
        const float* __restrict__ a1, const float* __restrict__ a2,
        float* __restrict__ s1o, float* __restrict__ s2o) {
    __shared__ __half As[2][64*AS_H];
    __shared__ __half Bs[2][32*BS_H];
    __shared__ float sRed[4][16][2][2];
    int z = blockIdx.z;
    Ah += (long)(z / zDivA) * sA;
    Bh += (long)(z % zModB) * sB;
    float*  Cf = (float*)Cout + (CH ? 0 : (long)z * sC);
    __half* Ch = (__half*)Cout + (CH ? (long)z * sC : 0);

    int n0 = blockIdx.x * 64, m0 = blockIdx.y * 64;
    int t = threadIdx.x, lane = t & 31, w = t >> 5;
    int gid = lane >> 2, tig = lane & 3;
    int mrow = (w & 3) * 16, ncol = (w >> 2) * 32;
    int l16 = lane & 15, lhi = (lane >> 4) * 8;

    int am_ = t >> 2, akq = (t & 3) * 8;
    int bkk = t >> 3, bnq = (t & 7) * 8;
    long aoff = (long)(m0 + am_)*K + akq;
    long boff = (long)bkk*N + n0 + bnq;
    uint32_t adst[2] = { smem_u32(&As[0][am_*AS_H + akq]), smem_u32(&As[1][am_*AS_H + akq]) };
    uint32_t bdst[2] = { smem_u32(&Bs[0][bkk*BS_H + bnq]), smem_u32(&Bs[1][bkk*BS_H + bnq]) };
    uint32_t aA[2] = { smem_u32(&As[0][(mrow+l16)*AS_H + lhi]), smem_u32(&As[1][(mrow+l16)*AS_H + lhi]) };
    uint32_t aB[2] = { smem_u32(&Bs[0][l16*BS_H + ncol + lhi]), smem_u32(&Bs[1][l16*BS_H + ncol + lhi]) };

    float acc[4][4];
#pragma unroll
    for (int nt = 0; nt < 4; nt++)
#pragma unroll
        for (int q = 0; q < 4; q++) acc[nt][q] = 0.f;

    int T = K >> 5;
    cp16(adst[0], Ah + aoff);
    cp16(bdst[0], Bh + boff);
    CP_COMMIT;

    for (int tk = 0; tk < T; tk++) {
        int st = tk & 1;
        __syncthreads();
        if (tk+1 < T) {
            int k0 = (tk+1) << 5;
            cp16(adst[st^1], Ah + aoff + k0);
            cp16(bdst[st^1], Bh + boff + (long)k0*N);
            CP_COMMIT;
            CP_WAIT1;
        } else {
            CP_WAIT0;
        }
        __syncthreads();
#pragma unroll
        for (int ks = 0; ks < 2; ks++) {
            uint32_t af[4];
            ldsm_x4(af, aA[st] + ks*32);
            uint32_t bfr[2][4];
#pragma unroll
            for (int ntp = 0; ntp < 2; ntp++)
                ldsm_x4t(bfr[ntp], aB[st] + (ks*16*BS_H + ntp*16)*2);
#pragma unroll
            for (int nt = 0; nt < 4; nt++)
                mma_f16(acc[nt], af, bfr[nt>>1][(nt&1)*2], bfr[nt>>1][(nt&1)*2+1]);
        }
    }
    // epilogue (fragment layout)
    float stS[4][2], stQ[4][2];
    float d1a = 0.f, d1b = 0.f, d2a = 0.f, d2b = 0.f;
    const float* a1e = a1 ? a1 + (z % 3)*SLOTS : nullptr;
    const float* a2e = a2 ? a2 + (z % 3)*SLOTS : nullptr;
    long r0 = m0 + mrow + gid, r1 = r0 + 8;
#pragma unroll
    for (int nt = 0; nt < 4; nt++) {
        int c = n0 + ncol + nt*8 + 2*tig;
        float v0 = alpha*acc[nt][0], v1 = alpha*acc[nt][1];
        float v2 = alpha*acc[nt][2], v3 = alpha*acc[nt][3];
        if (R) {
            float2 ra = *(const float2*)(R + r0*N + c);
            float2 rb = *(const float2*)(R + r1*N + c);
            v0 += beta*ra.x; v1 += beta*ra.y; v2 += beta*rb.x; v3 += beta*rb.y;
        }
        if (CH) {
            *(__half2*)(Ch + r0*N + c) = __floats2half2_rn(v0, v1);
            *(__half2*)(Ch + r1*N + c) = __floats2half2_rn(v2, v3);
        } else {
            *(float2*)(Cf + r0*N + c) = make_float2(v0, v1);
            *(float2*)(Cf + r1*N + c) = make_float2(v2, v3);
        }
        if (a1e) {
            float w10 = a1e[c]*LOG2E, w11 = a1e[c+1]*LOG2E;
            float w20 = a2e[c]*LOG2E, w21 = a2e[c+1]*LOG2E;
            d1a += v0*w10 + v1*w11; d1b += v2*w10 + v3*w11;
            d2a += v0*w20 + v1*w21; d2b += v2*w20 + v3*w21;
        }
        stS[nt][0] = v0 + v2; stS[nt][1] = v1 + v3;
        stQ[nt][0] = v0*v0 + v2*v2; stQ[nt][1] = v1*v1 + v3*v3;
    }
    if (a1) {
        d1a += __shfl_down_sync(0xffffffffu, d1a, 1); d1a += __shfl_down_sync(0xffffffffu, d1a, 2);
        d1b += __shfl_down_sync(0xffffffffu, d1b, 1); d1b += __shfl_down_sync(0xffffffffu, d1b, 2);
        d2a += __shfl_down_sync(0xffffffffu, d2a, 1); d2a += __shfl_down_sync(0xffffffffu, d2a, 2);
        d2b += __shfl_down_sync(0xffffffffu, d2b, 1); d2b += __shfl_down_sync(0xffffffffu, d2b, 2);
        int mg = w & 3, half = w >> 2;
        if (tig == 0) {
            sRed[mg][gid][0][half]   = d1a;
            sRed[mg][gid+8][0][half] = d1b;
            sRed[mg][gid][1][half]   = d2a;
            sRed[mg][gid+8][1][half] = d2b;
        }
        __syncthreads();
        if (t < 128) {
            int tmg = t >> 5, rem = t & 31, row16 = rem & 15, which = rem >> 4;
            float v = sRed[tmg][row16][which][0] + sRed[tmg][row16][which][1];
            int mhead = n0 >> 6;
            long row = m0 + tmg*16 + row16;
            float* dst = (which ? s2o : s1o) + (z*4 + mhead)*NN + row;
            *dst = v;
        }
    }
    if (stats) {
#pragma unroll
        for (int nt = 0; nt < 4; nt++) {
#pragma unroll
            for (int cc = 0; cc < 2; cc++) {
                float s = stS[nt][cc], q = stQ[nt][cc];
#pragma unroll
                for (int off = 16; off >= 4; off >>= 1) {
                    s += __shfl_down_sync(0xffffffffu, s, off);
                    q += __shfl_down_sync(0xffffffffu, q, off);
                }
                if (lane < 4) {
                    int col = n0 + ncol + nt*8 + 2*lane + cc;
                    atomicAdd(&stats[col], s);
                    atomicAdd(&stats[N + col], q);
                }
            }
        }
    }
}

// ---------------- attention v5: half2 softmax (ex2.f16x2) + packed mask ----------------
#define SWH_H 264
#define SP_H  40
__global__ void __launch_bounds__(256, 3) att5_kernel(
        const unsigned short* __restrict__ pm, const __half* __restrict__ Wh,
        const float* __restrict__ s1, const float* __restrict__ s2,
        __half* __restrict__ H) {
    __shared__ __half sWh[2][32*SWH_H];
    __shared__ __half sP[4*32*SP_H];
    __shared__ float sDen[1024];
    __shared__ float sDen2[128];

    const int be = blockIdx.y;
    const int b  = be / 3, e = be % 3;
    const int i0 = blockIdx.x * 32;
    const int t  = threadIdx.x;
    const int lane = t & 31;
    const int w  = t >> 5;
    const int gid = lane >> 2, tig = lane & 3;
    const int l16 = lane & 15, lhi = (lane >> 4) * 8;

    const int ip = t >> 3;
    const int jg = t & 7;
    const int am = w >> 1;
    const int nh = (w & 1) * 32;

    const __half2 c001 = __float2half2_rn(0.01f);

    float s1v[4];
#pragma unroll
    for (int m = 0; m < 4; m++) s1v[m] = s1[(be*4+m)*NN + i0 + ip];

    float den[4] = {0.f,0.f,0.f,0.f};
    float acc[2][4][4];
#pragma unroll
    for (int mt = 0; mt < 2; mt++)
#pragma unroll
        for (int nt = 0; nt < 4; nt++)
#pragma unroll
            for (int q = 0; q < 4; q++) acc[mt][nt][q] = 0.f;

    const uint32_t* pmRow = (const uint32_t*)pm + ((long)be*NN + i0 + ip)*32;
    const __half* WhB = Wh + (long)be*NN*SLOTS;
    const float* s2b  = s2 + be*4*NN;

    int off[4];
    uint32_t wdst[2][4];
#pragma unroll
    for (int k = 0; k < 4; k++) {
        int idx = t + k*256;
        int jj = idx >> 5, cq = idx & 31;
        off[k] = jj*256 + cq*8;
        wdst[0][k] = smem_u32(&sWh[0][jj*SWH_H + cq*8]);
        wdst[1][k] = smem_u32(&sWh[1][jj*SWH_H + cq*8]);
    }
    uint32_t aP = smem_u32(&sP[(am*32 + l16)*SP_H + lhi]);
    uint32_t aW[2] = { smem_u32(&sWh[0][l16*SWH_H + am*64 + nh + lhi]),
                       smem_u32(&sWh[1][l16*SWH_H + am*64 + nh + lhi]) };

#pragma unroll
    for (int k = 0; k < 4; k++) cp16(wdst[0][k], WhB + off[k]);
    CP_COMMIT;

    for (int jt = 0; jt < 32; jt++) {
        const int j0 = jt << 5;
        const int st = jt & 1;
        __syncthreads();
        if (jt+1 < 32) {
            const __half* src = WhB + (long)(j0+32)*SLOTS;
#pragma unroll
            for (int k = 0; k < 4; k++) cp16(wdst[st^1][k], src + off[k]);
            CP_COMMIT;
        }
        {
            uint32_t nib = pmRow[jt] >> (jg*4);
            __half2 hm01 = __floats2half2_rn((float)(nib & 1u), (float)((nib >> 1) & 1u));
            __half2 hm23 = __floats2half2_rn((float)((nib >> 2) & 1u), (float)((nib >> 3) & 1u));
#pragma unroll
            for (int m = 0; m < 4; m++) {
                float4 s4 = *(const float4*)(s2b + m*NN + j0 + jg*4);
                __half2 x01 = __floats2half2_rn(s1v[m]+s4.x, s1v[m]+s4.y);
                __half2 x23 = __floats2half2_rn(s1v[m]+s4.z, s1v[m]+s4.w);
                x01 = __hmax2(x01, __hmul2(x01, c001));
                x23 = __hmax2(x23, __hmul2(x23, c001));
                __half2 p01 = __hmul2(ex2_h2(x01), hm01);
                __half2 p23 = __hmul2(ex2_h2(x23), hm23);
                __half2 hp[2] = {p01, p23};
                *(uint2*)&sP[(m*32 + ip)*SP_H + jg*4] = *(uint2*)hp;
                float2 df = __half22float2(__hadd2(p01, p23));
                den[m] += df.x + df.y;
            }
        }
        if (jt+1 < 32) { CP_WAIT1; } else { CP_WAIT0; }
        __syncthreads();
#pragma unroll
        for (int ks = 0; ks < 2; ks++) {
            uint32_t bfr[2][4];
#pragma unroll
            for (int ntp = 0; ntp < 2; ntp++)
                ldsm_x4t(bfr[ntp], aW[st] + (ks*16*SWH_H + ntp*16)*2);
#pragma unroll
            for (int mt = 0; mt < 2; mt++) {
                uint32_t af[4];
                ldsm_x4(af, aP + (mt*16*SP_H + ks*16)*2);
#pragma unroll
                for (int nt = 0; nt < 4; nt++)
                    mma_f16(acc[mt][nt], af, bfr[nt>>1][(nt&1)*2], bfr[nt>>1][(nt&1)*2+1]);
            }
        }
    }
    __syncthreads();
#pragma unroll
    for (int m = 0; m < 4; m++) sDen[(m*32 + ip)*8 + jg] = den[m];
    __syncthreads();
    if (t < 128) {
        float s = 0.f;
#pragma unroll
        for (int r = 0; r < 8; r++) s += sDen[t*8 + r];
        sDen2[t] = 1.f / fmaxf(s, 1e-30f);
    }
    __syncthreads();
#pragma unroll
    for (int mt = 0; mt < 2; mt++) {
        int r0 = mt*16 + gid;
        float inv0 = sDen2[am*32 + r0];
        float inv1 = sDen2[am*32 + r0 + 8];
        long row0 = (long)(b*NN) + i0 + r0;
        long row1 = row0 + 8;
#pragma unroll
        for (int nt = 0; nt < 4; nt++) {
            int col = am*192 + e*64 + nh + nt*8 + 2*tig;
            float v0 = acc[mt][nt][0]*inv0, v1 = acc[mt][nt][1]*inv0;
            float v2 = acc[mt][nt][2]*inv1, v3 = acc[mt][nt][3]*inv1;
            v0 = (v0 > 0.f) ? v0 : expm1f(v0);
            v1 = (v1 > 0.f) ? v1 : expm1f(v1);
            v2 = (v2 > 0.f) ? v2 : expm1f(v2);
            v3 = (v3 > 0.f) ? v3 : expm1f(v3);
            *(__half2*)(H + row0*HC + col) = __floats2half2_rn(v0, v1);
            *(__half2*)(H + row1*HC + col) = __floats2half2_rn(v2, v3);
        }
    }
}

// ---------------- batchnorm normalize: fp32 in -> fp16 (+opt fp32) out ----------------
__global__ void norm2_kernel(const float* __restrict__ Y, __half* __restrict__ oh,
                             float* __restrict__ of,
                             const float* __restrict__ stats,
                             const float* __restrict__ g, const float* __restrict__ bb,
                             int N, int elu) {
    int i4 = blockIdx.x*blockDim.x + threadIdx.x;
    if (i4 >= ROWS*N/4) return;
    int i = i4*4;
    int col = i & (N - 1);
    const float invM = 1.f / (float)ROWS;
    float4 y = *(const float4*)(Y + i);
    float4 sm = *(const float4*)(stats + col);
    float4 sq = *(const float4*)(stats + N + col);
    float4 gg = *(const float4*)(g + col);
    float4 bv = *(const float4*)(bb + col);
    float m0 = sm.x*invM, m1 = sm.y*invM, m2 = sm.z*invM, m3 = sm.w*invM;
    float w0 = gg.x * rsqrtf(sq.x*invM - m0*m0 + 1e-5f);
    float w1 = gg.y * rsqrtf(sq.y*invM - m1*m1 + 1e-5f);
    float w2 = gg.z * rsqrtf(sq.z*invM - m2*m2 + 1e-5f);
    float w3 = gg.w * rsqrtf(sq.w*invM - m3*m3 + 1e-5f);
    float v0 = (y.x - m0)*w0 + bv.x;
    float v1 = (y.y - m1)*w1 + bv.y;
    float v2 = (y.z - m2)*w2 + bv.z;
    float v3 = (y.w - m3)*w3 + bv.w;
    if (elu) {
        v0 = (v0 > 0.f) ? v0 : expm1f(v0);
        v1 = (v1 > 0.f) ? v1 : expm1f(v1);
        v2 = (v2 > 0.f) ? v2 : expm1f(v2);
        v3 = (v3 > 0.f) ? v3 : expm1f(v3);
    }
    if (oh) {
        *(__half2*)(oh + i)     = __floats2half2_rn(v0, v1);
        *(__half2*)(oh + i + 2) = __floats2half2_rn(v2, v3);
    }
    if (of) *(float4*)(of + i) = make_float4(v0, v1, v2, v3);
}

// ---------------- launch ----------------
extern "C" void kernel_launch(void* const* d_in, const int* in_sizes, int n_in,
                              void* d_out, int out_size) {
    const int*   A      = (const int*)  d_in[0];
    const float* X      = (const float*)d_in[1];
    const float* Ws     = (const float*)d_in[3];
    const float* a1     = (const float*)d_in[4];
    const float* a2     = (const float*)d_in[5];
    const float* W1     = (const float*)d_in[6];
    const float* bn1_g  = (const float*)d_in[7];
    const float* bn1_b  = (const float*)d_in[8];
    const float* e_l0   = (const float*)d_in[9];
    const float* e_bn0g = (const float*)d_in[10];
    const float* e_bn0b = (const float*)d_in[11];
    const float* e_l1   = (const float*)d_in[12];
    const float* e_bn1g = (const float*)d_in[13];
    const float* e_bn1b = (const float*)d_in[14];
    const float* e_l2   = (const float*)d_in[15];
    const float* bn2_g  = (const float*)d_in[16];
    const float* bn2_b  = (const float*)d_in[17];
    float* out = (float*)d_out;

    float *ps1, *ps2, *pHnF, *pA, *pSt;
    __half *pXH, *pWtH, *pW1H, *pL0H, *pL1H, *pL2H, *pWh, *pH, *pHnH, *pZ0, *pZ1;
    unsigned short* ppm;
    cudaGetSymbolAddress((void**)&pXH,  d_XH);
    cudaGetSymbolAddress((void**)&pWtH, d_WtH);
    cudaGetSymbolAddress((void**)&pW1H, d_W1H);
    cudaGetSymbolAddress((void**)&pL0H, d_L0H);
    cudaGetSymbolAddress((void**)&pL1H, d_L1H);
    cudaGetSymbolAddress((void**)&pL2H, d_L2H);
    cudaGetSymbolAddress((void**)&pWh,  d_Wh);
    cudaGetSymbolAddress((void**)&pH,   d_H);
    cudaGetSymbolAddress((void**)&pHnH, d_HnH);
    cudaGetSymbolAddress((void**)&pHnF, d_HnF);
    cudaGetSymbolAddress((void**)&pZ0,  d_Z0h);
    cudaGetSymbolAddress((void**)&pZ1,  d_Z1h);
    cudaGetSymbolAddress((void**)&ps1,  d_s1);
    cudaGetSymbolAddress((void**)&ps2,  d_s2);
    cudaGetSymbolAddress((void**)&ppm,  d_pm);
    cudaGetSymbolAddress((void**)&pA,   d_bufA);
    cudaGetSymbolAddress((void**)&pSt,  d_stats);

    static cudaStream_t s2str = nullptr;
    static cudaEvent_t evFork = nullptr, evJoin = nullptr;
    if (!s2str) {
        cudaStreamCreateWithFlags(&s2str, cudaStreamNonBlocking);
        cudaEventCreateWithFlags(&evFork, cudaEventDisableTiming);
        cudaEventCreateWithFlags(&evJoin, cudaEventDisableTiming);
    }

    // Fork: edge_cat + mask on side stream, overlapping main-stream prologue only
    cudaEventRecord(evFork, 0);
    cudaStreamWaitEvent(s2str, evFork, 0);
    edge2_kernel<<<ROWS, 256, 0, s2str>>>(A, out + ROWS*FF, ppm);
    cudaEventRecord(evJoin, s2str);

    // Main prologue: all conversions + relayout + stats zero in ONE launch
    prep_kernel<<<PREP_BLOCKS, 256>>>(X, W1, e_l0, e_l1, e_l2, Ws, (float4*)pSt);

    // Wh projection + direct s1/s2 (log2e-scaled)
    gemm4_kernel<1><<<dim3(SLOTS/64, NN/64, BE), 256>>>(
        pXH, pWtH, pWh, NN, SLOTS, FF,
        (long)NN*FF, (long)FF*SLOTS, (long)NN*SLOTS, EE, EE,
        1.f, nullptr, 0.f, nullptr, a1, a2, ps1, ps2);

    cudaStreamWaitEvent(0, evJoin, 0);   // edge drained before att (protect L2 reuse)

    // fused masked softmax + P@Wh + ELU -> H
    att5_kernel<<<dim3(NN/32, BE), 256>>>(ppm, pWh, ps1, ps2, pH);

    // H @ W1 * 0.5 + 0.5*X -> bufA, stats0; bn1 -> HnH + HnF
    gemm4_kernel<0><<<dim3(FF/64, ROWS/64, 1), 256>>>(
        pH, pW1H, pA, ROWS, FF, HC, 0,0,0, 1,1,
        0.5f, X, 0.5f, pSt + 0, nullptr, nullptr, nullptr, nullptr);
    norm2_kernel<<<(ROWS*FF/4+255)/256, 256>>>(pA, pHnH, pHnF, pSt + 0, bn1_g, bn1_b, FF, 0);

    // Hn @ e_l0 -> bufA, stats1; elu(bn) -> Z0
    gemm4_kernel<0><<<dim3(L0C/64, ROWS/64, 1), 256>>>(
        pHnH, pL0H, pA, ROWS, L0C, FF, 0,0,0, 1,1,
        1.f, nullptr, 0.f, pSt + 512, nullptr, nullptr, nullptr, nullptr);
    norm2_kernel<<<(ROWS*L0C/4+255)/256, 256>>>(pA, pZ0, nullptr, pSt + 512, e_bn0g, e_bn0b, L0C, 1);

    // Z0 @ e_l1 -> bufA, stats2; elu(bn) -> Z1
    gemm4_kernel<0><<<dim3(L1C/64, ROWS/64, 1), 256>>>(
        pZ0, pL1H, pA, ROWS, L1C, L0C, 0,0,0, 1,1,
        1.f, nullptr, 0.f, pSt + 1024, nullptr, nullptr, nullptr, nullptr);
    norm2_kernel<<<(ROWS*L1C/4+255)/256, 256>>>(pA, pZ1, nullptr, pSt + 1024, e_bn1g, e_bn1b, L1C, 1);

    // Z1 @ e_l2 + HnF -> bufA, stats3; bn2 -> out
    gemm4_kernel<0><<<dim3(FF/64, ROWS/64, 1), 256>>>(
        pZ1, pL2H, pA, ROWS, FF, L1C, 0,0,0, 1,1,
        1.f, pHnF, 1.f, pSt + 1536, nullptr, nullptr, nullptr, nullptr);
    norm2_kernel<<<(ROWS*FF/4+255)/256, 256>>>(pA, nullptr, out, pSt + 1536, bn2_g, bn2_b, FF, 0);
}

// round 13
// speedup vs baseline: 1.1271x; 1.0321x over previous
// GCRN fused pipeline — R13: p-phase diet (half2 s2, mask LUT, mma-computed
// denominator). Graph topology identical to R12 winner.
#include <cuda_runtime.h>
#include <cuda_fp16.h>
#include <math.h>
#include <stdint.h>

// Problem constants
#define BB 8
#define NN 1024
#define FF 128
#define GG 64
#define MM 4
#define EE 3
#define BE (BB*EE)        // 24
#define SLOTS (MM*GG)     // 256
#define ROWS (BB*NN)      // 8192
#define HC (MM*EE*GG)     // 768
#define L0C 256
#define L1C 256
#define LOG2E 1.44269504f

// ---------------- scratch ----------------
__device__ __half d_XH [ROWS*FF];
__device__ __half d_WtH[EE*FF*SLOTS];
__device__ __half d_W1H[HC*FF];
__device__ __half d_L0H[FF*L0C];
__device__ __half d_L1H[L0C*L1C];
__device__ __half d_L2H[L1C*FF];
__device__ __half d_Wh [BE*NN*SLOTS];        // [be][n][m*64+g]
__device__ __half d_H  [ROWS*HC];            // [b*N+n][m*192+e*64+g]
__device__ __half d_HnH[ROWS*FF];
__device__ float  d_HnF[ROWS*FF];
__device__ __half d_Z0h[ROWS*L0C];
__device__ __half d_Z1h[ROWS*L1C];
__device__ float  d_s1[BE*MM*NN];            // pre-scaled by log2(e), fp32
__device__ __half d_s2h[BE*MM*NN];           // pre-scaled by log2(e), fp16
__device__ unsigned short d_pm[BE*NN*64];    // bit-packed mask
__device__ float  d_bufA[ROWS*L0C];
__device__ float  d_stats[4*512];

// ---------------- helpers ----------------
__device__ __forceinline__ uint32_t smem_u32(const void* p) {
    return (uint32_t)__cvta_generic_to_shared(p);
}
__device__ __forceinline__ void cp16(uint32_t dst, const void* src) {
    asm volatile("cp.async.cg.shared.global [%0], [%1], 16;" :: "r"(dst), "l"(src) : "memory");
}
#define CP_COMMIT asm volatile("cp.async.commit_group;" ::: "memory")
#define CP_WAIT1  asm volatile("cp.async.wait_group 1;" ::: "memory")
#define CP_WAIT0  asm volatile("cp.async.wait_group 0;" ::: "memory")

__device__ __forceinline__ void ldsm_x4(uint32_t* r, uint32_t addr) {
    asm volatile("ldmatrix.sync.aligned.m8n8.x4.shared.b16 {%0,%1,%2,%3}, [%4];"
        : "=r"(r[0]), "=r"(r[1]), "=r"(r[2]), "=r"(r[3]) : "r"(addr));
}
__device__ __forceinline__ void ldsm_x4t(uint32_t* r, uint32_t addr) {
    asm volatile("ldmatrix.sync.aligned.m8n8.x4.trans.shared.b16 {%0,%1,%2,%3}, [%4];"
        : "=r"(r[0]), "=r"(r[1]), "=r"(r[2]), "=r"(r[3]) : "r"(addr));
}
__device__ __forceinline__ void mma_f16(float* d, const uint32_t* a, uint32_t b0, uint32_t b1) {
    asm volatile(
        "mma.sync.aligned.m16n8k16.row.col.f32.f16.f16.f32 "
        "{%0,%1,%2,%3}, {%4,%5,%6,%7}, {%8,%9}, {%0,%1,%2,%3};"
        : "+f"(d[0]), "+f"(d[1]), "+f"(d[2]), "+f"(d[3])
        : "r"(a[0]), "r"(a[1]), "r"(a[2]), "r"(a[3]), "r"(b0), "r"(b1));
}
__device__ __forceinline__ __half2 ex2_h2(__half2 x) {
    uint32_t xi = *(uint32_t*)&x, r;
    asm("ex2.approx.f16x2 %0, %1;" : "=r"(r) : "r"(xi));
    return *(__half2*)&r;
}

// ---------------- prep: cvt(X,W1,L0,L1,L2) + Ws relayout + stats zero, one launch ----
#define CVT_NX (ROWS*FF)
#define CVT_NW1 (HC*FF)
#define CVT_NL0 (FF*L0C)
#define CVT_NL1 (L0C*L1C)
#define CVT_NL2 (L1C*FF)
#define CVT_TOT4 ((CVT_NX+CVT_NW1+CVT_NL0+CVT_NL1+CVT_NL2)/4)
#define CVT_BLOCKS ((CVT_TOT4+255)/256)
#define WT_BLOCKS 384
#define PREP_BLOCKS (CVT_BLOCKS + WT_BLOCKS + 2)
__global__ void prep_kernel(const float* __restrict__ X, const float* __restrict__ W1,
                            const float* __restrict__ L0, const float* __restrict__ L1,
                            const float* __restrict__ L2, const float* __restrict__ Ws,
                            float4* __restrict__ stats) {
    int bx = blockIdx.x;
    if (bx < CVT_BLOCKS) {
        int i4 = bx*256 + threadIdx.x;
        if (i4 >= CVT_TOT4) return;
        int i = i4*4;
        const float* src; __half* dst;
        if (i < CVT_NX) { src = X; dst = d_XH; }
        else if ((i -= CVT_NX) < CVT_NW1) { src = W1; dst = d_W1H; }
        else if ((i -= CVT_NW1) < CVT_NL0) { src = L0; dst = d_L0H; }
        else if ((i -= CVT_NL0) < CVT_NL1) { src = L1; dst = d_L1H; }
        else { i -= CVT_NL1; src = L2; dst = d_L2H; }
        float4 v = *(const float4*)(src + i);
        *(__half2*)(dst + i)     = __floats2half2_rn(v.x, v.y);
        *(__half2*)(dst + i + 2) = __floats2half2_rn(v.z, v.w);
    } else if (bx < CVT_BLOCKS + WT_BLOCKS) {
        int idx = (bx - CVT_BLOCKS)*256 + threadIdx.x;
        int e = idx >> 15;
        int r = idx & 32767;
        int f = r >> 8;
        int c = r & 255;
        int m = c >> 6, g = c & 63;
        d_WtH[idx] = __float2half(Ws[e*32768 + m*8192 + f*64 + g]);
    } else {
        int i = (bx - CVT_BLOCKS - WT_BLOCKS)*256 + threadIdx.x;
        if (i < 512) stats[i] = make_float4(0.f,0.f,0.f,0.f);
    }
}

// edge v2: smem transpose for coalesced stores + ballot mask, single A read
__global__ void __launch_bounds__(256) edge2_kernel(
        const int* __restrict__ A, float* __restrict__ out,
        unsigned short* __restrict__ pm) {
    __shared__ float sv[3072];
    int bi = blockIdx.x;
    int b = bi >> 10, i = bi & 1023;
    int t = threadIdx.x;
    int lane = t & 31, w = t >> 5;
#pragma unroll
    for (int e = 0; e < 3; e++) {
        const int* src = A + (((long)(b*3+e) << 10) + i)*1024;
        uint32_t* pmW = (uint32_t*)pm + (((long)(b*3+e) << 10) + i)*32;
#pragma unroll
        for (int k = 0; k < 4; k++) {
            int j = t + k*256;
            int a = __ldcs(src + j);
            sv[j*3 + e] = (float)a;
            unsigned bal = __ballot_sync(0xffffffffu, a > 0);
            if (lane == 0) pmW[k*8 + w] = bal;
        }
    }
    __syncthreads();
    float4* o = (float4*)(out + (long)bi*3072);
    const float4* s4 = (const float4*)sv;
#pragma unroll
    for (int k = 0; k < 3; k++) __stcs(o + t + k*256, s4[t + k*256]);
}

// ---------------- gemm4: fp16 x fp16 -> fp32, cp.async 2-stage pipeline ----------------
// 64x64 tile, k-tile 32, 8 warps each 16m x 32n. Residual/stats fusion; projection
// variant writes s1 (fp32) / s2 (fp16) directly (block owns its rows exclusively).
#define AS_H 40
#define BS_H 72
template <int CH>
__global__ void __launch_bounds__(256) gemm4_kernel(
        const __half* __restrict__ Ah, const __half* __restrict__ Bh, void* __restrict__ Cout,
        int M, int N, int K,
        long sA, long sB, long sC, int zDivA, int zModB,
        float alpha, const float* __restrict__ R, float beta,
        float* __restrict__ stats,
        const float* __restrict__ a1, const float* __restrict__ a2,
        float* __restrict__ s1o, __half* __restrict__ s2o) {
    __shared__ __half As[2][64*AS_H];
    __shared__ __half Bs[2][32*BS_H];
    __shared__ float sRed[4][16][2][2];
    int z = blockIdx.z;
    Ah += (long)(z / zDivA) * sA;
    Bh += (long)(z % zModB) * sB;
    float*  Cf = (float*)Cout + (CH ? 0 : (long)z * sC);
    __half* Ch = (__half*)Cout + (CH ? (long)z * sC : 0);

    int n0 = blockIdx.x * 64, m0 = blockIdx.y * 64;
    int t = threadIdx.x, lane = t & 31, w = t >> 5;
    int gid = lane >> 2, tig = lane & 3;
    int mrow = (w & 3) * 16, ncol = (w >> 2) * 32;
    int l16 = lane & 15, lhi = (lane >> 4) * 8;

    int am_ = t >> 2, akq = (t & 3) * 8;
    int bkk = t >> 3, bnq = (t & 7) * 8;
    long aoff = (long)(m0 + am_)*K + akq;
    long boff = (long)bkk*N + n0 + bnq;
    uint32_t adst[2] = { smem_u32(&As[0][am_*AS_H + akq]), smem_u32(&As[1][am_*AS_H + akq]) };
    uint32_t bdst[2] = { smem_u32(&Bs[0][bkk*BS_H + bnq]), smem_u32(&Bs[1][bkk*BS_H + bnq]) };
    uint32_t aA[2] = { smem_u32(&As[0][(mrow+l16)*AS_H + lhi]), smem_u32(&As[1][(mrow+l16)*AS_H + lhi]) };
    uint32_t aB[2] = { smem_u32(&Bs[0][l16*BS_H + ncol + lhi]), smem_u32(&Bs[1][l16*BS_H + ncol + lhi]) };

    float acc[4][4];
#pragma unroll
    for (int nt = 0; nt < 4; nt++)
#pragma unroll
        for (int q = 0; q < 4; q++) acc[nt][q] = 0.f;

    int T = K >> 5;
    cp16(adst[0], Ah + aoff);
    cp16(bdst[0], Bh + boff);
    CP_COMMIT;

    for (int tk = 0; tk < T; tk++) {
        int st = tk & 1;
        __syncthreads();
        if (tk+1 < T) {
            int k0 = (tk+1) << 5;
            cp16(adst[st^1], Ah + aoff + k0);
            cp16(bdst[st^1], Bh + boff + (long)k0*N);
            CP_COMMIT;
            CP_WAIT1;
        } else {
            CP_WAIT0;
        }
        __syncthreads();
#pragma unroll
        for (int ks = 0; ks < 2; ks++) {
            uint32_t af[4];
            ldsm_x4(af, aA[st] + ks*32);
            uint32_t bfr[2][4];
#pragma unroll
            for (int ntp = 0; ntp < 2; ntp++)
                ldsm_x4t(bfr[ntp], aB[st] + (ks*16*BS_H + ntp*16)*2);
#pragma unroll
            for (int nt = 0; nt < 4; nt++)
                mma_f16(acc[nt], af, bfr[nt>>1][(nt&1)*2], bfr[nt>>1][(nt&1)*2+1]);
        }
    }
    // epilogue (fragment layout)
    float stS[4][2], stQ[4][2];
    float d1a = 0.f, d1b = 0.f, d2a = 0.f, d2b = 0.f;
    const float* a1e = a1 ? a1 + (z % 3)*SLOTS : nullptr;
    const float* a2e = a2 ? a2 + (z % 3)*SLOTS : nullptr;
    long r0 = m0 + mrow + gid, r1 = r0 + 8;
#pragma unroll
    for (int nt = 0; nt < 4; nt++) {
        int c = n0 + ncol + nt*8 + 2*tig;
        float v0 = alpha*acc[nt][0], v1 = alpha*acc[nt][1];
        float v2 = alpha*acc[nt][2], v3 = alpha*acc[nt][3];
        if (R) {
            float2 ra = *(const float2*)(R + r0*N + c);
            float2 rb = *(const float2*)(R + r1*N + c);
            v0 += beta*ra.x; v1 += beta*ra.y; v2 += beta*rb.x; v3 += beta*rb.y;
        }
        if (CH) {
            *(__half2*)(Ch + r0*N + c) = __floats2half2_rn(v0, v1);
            *(__half2*)(Ch + r1*N + c) = __floats2half2_rn(v2, v3);
        } else {
            *(float2*)(Cf + r0*N + c) = make_float2(v0, v1);
            *(float2*)(Cf + r1*N + c) = make_float2(v2, v3);
        }
        if (a1e) {
            float w10 = a1e[c]*LOG2E, w11 = a1e[c+1]*LOG2E;
            float w20 = a2e[c]*LOG2E, w21 = a2e[c+1]*LOG2E;
            d1a += v0*w10 + v1*w11; d1b += v2*w10 + v3*w11;
            d2a += v0*w20 + v1*w21; d2b += v2*w20 + v3*w21;
        }
        stS[nt][0] = v0 + v2; stS[nt][1] = v1 + v3;
        stQ[nt][0] = v0*v0 + v2*v2; stQ[nt][1] = v1*v1 + v3*v3;
    }
    if (a1) {
        d1a += __shfl_down_sync(0xffffffffu, d1a, 1); d1a += __shfl_down_sync(0xffffffffu, d1a, 2);
        d1b += __shfl_down_sync(0xffffffffu, d1b, 1); d1b += __shfl_down_sync(0xffffffffu, d1b, 2);
        d2a += __shfl_down_sync(0xffffffffu, d2a, 1); d2a += __shfl_down_sync(0xffffffffu, d2a, 2);
        d2b += __shfl_down_sync(0xffffffffu, d2b, 1); d2b += __shfl_down_sync(0xffffffffu, d2b, 2);
        int mg = w & 3, half = w >> 2;
        if (tig == 0) {
            sRed[mg][gid][0][half]   = d1a;
            sRed[mg][gid+8][0][half] = d1b;
            sRed[mg][gid][1][half]   = d2a;
            sRed[mg][gid+8][1][half] = d2b;
        }
        __syncthreads();
        if (t < 128) {
            int tmg = t >> 5, rem = t & 31, row16 = rem & 15, which = rem >> 4;
            float v = sRed[tmg][row16][which][0] + sRed[tmg][row16][which][1];
            int mhead = n0 >> 6;
            long row = m0 + tmg*16 + row16;
            long idx = (long)(z*4 + mhead)*NN + row;
            if (which) s2o[idx] = __float2half(v);
            else       s1o[idx] = v;
        }
    }
    if (stats) {
#pragma unroll
        for (int nt = 0; nt < 4; nt++) {
#pragma unroll
            for (int cc = 0; cc < 2; cc++) {
                float s = stS[nt][cc], q = stQ[nt][cc];
#pragma unroll
                for (int off = 16; off >= 4; off >>= 1) {
                    s += __shfl_down_sync(0xffffffffu, s, off);
                    q += __shfl_down_sync(0xffffffffu, q, off);
                }
                if (lane < 4) {
                    int col = n0 + ncol + nt*8 + 2*lane + cc;
                    atomicAdd(&stats[col], s);
                    atomicAdd(&stats[N + col], q);
                }
            }
        }
    }
}

// ---------------- attention v6: half2 p-phase (LUT mask, half2 s2) + mma denominator ----
#define SWH_H 264
#define SP_H  40
__global__ void __launch_bounds__(256, 3) att6_kernel(
        const unsigned short* __restrict__ pm, const __half* __restrict__ Wh,
        const float* __restrict__ s1, const __half* __restrict__ s2h,
        __half* __restrict__ H) {
    __shared__ __half sWh[2][32*SWH_H];
    __shared__ __half sP[4*32*SP_H];
    __shared__ float sDen2[128];
    __shared__ uint2 sLut[16];

    const int be = blockIdx.y;
    const int b  = be / 3, e = be % 3;
    const int i0 = blockIdx.x * 32;
    const int t  = threadIdx.x;
    const int lane = t & 31;
    const int w  = t >> 5;
    const int gid = lane >> 2, tig = lane & 3;
    const int l16 = lane & 15, lhi = (lane >> 4) * 8;

    const int ip = t >> 3;
    const int jg = t & 7;
    const int am = w >> 1;
    const int nh = (w & 1) * 32;

    const __half2 c001 = __float2half2_rn(0.01f);
    const uint32_t kONE = 0x3C003C00u;   // half2(1.0, 1.0)

    if (t < 16) {
        sLut[t] = make_uint2(
            ((t & 1) ? 0x3C00u : 0u) | ((t & 2) ? 0x3C000000u : 0u),
            ((t & 4) ? 0x3C00u : 0u) | ((t & 8) ? 0x3C000000u : 0u));
    }

    __half2 s1h[4];
#pragma unroll
    for (int m = 0; m < 4; m++)
        s1h[m] = __half2half2(__float2half(s1[(be*4+m)*NN + i0 + ip]));

    float acc[2][4][4];
#pragma unroll
    for (int mt = 0; mt < 2; mt++)
#pragma unroll
        for (int nt = 0; nt < 4; nt++)
#pragma unroll
            for (int q = 0; q < 4; q++) acc[mt][nt][q] = 0.f;
    float dacc[2][4];
#pragma unroll
    for (int mt = 0; mt < 2; mt++)
#pragma unroll
        for (int q = 0; q < 4; q++) dacc[mt][q] = 0.f;

    const uint32_t* pmRow = (const uint32_t*)pm + ((long)be*NN + i0 + ip)*32;
    const __half* WhB = Wh + (long)be*NN*SLOTS;
    const __half* s2b = s2h + be*4*NN;

    int off[4];
    uint32_t wdst[2][4];
#pragma unroll
    for (int k = 0; k < 4; k++) {
        int idx = t + k*256;
        int jj = idx >> 5, cq = idx & 31;
        off[k] = jj*256 + cq*8;
        wdst[0][k] = smem_u32(&sWh[0][jj*SWH_H + cq*8]);
        wdst[1][k] = smem_u32(&sWh[1][jj*SWH_H + cq*8]);
    }
    uint32_t aP = smem_u32(&sP[(am*32 + l16)*SP_H + lhi]);
    uint32_t aW[2] = { smem_u32(&sWh[0][l16*SWH_H + am*64 + nh + lhi]),
                       smem_u32(&sWh[1][l16*SWH_H + am*64 + nh + lhi]) };

#pragma unroll
    for (int k = 0; k < 4; k++) cp16(wdst[0][k], WhB + off[k]);
    CP_COMMIT;

    for (int jt = 0; jt < 32; jt++) {
        const int j0 = jt << 5;
        const int st = jt & 1;
        __syncthreads();
        if (jt+1 < 32) {
            const __half* src = WhB + (long)(j0+32)*SLOTS;
#pragma unroll
            for (int k = 0; k < 4; k++) cp16(wdst[st^1][k], src + off[k]);
            CP_COMMIT;
        }
        // p-phase: masked 2^(lrelu(s1+s2)), all-half2
        {
            uint32_t nib = (pmRow[jt] >> (jg*4)) & 15u;
            uint2 hm = sLut[nib];
            __half2 hm01 = *(__half2*)&hm.x, hm23 = *(__half2*)&hm.y;
#pragma unroll
            for (int m = 0; m < 4; m++) {
                uint2 s2r = *(const uint2*)(s2b + m*NN + j0 + jg*4);
                __half2 x01 = __hadd2(s1h[m], *(__half2*)&s2r.x);
                __half2 x23 = __hadd2(s1h[m], *(__half2*)&s2r.y);
                x01 = __hmax2(x01, __hmul2(x01, c001));
                x23 = __hmax2(x23, __hmul2(x23, c001));
                __half2 p01 = __hmul2(ex2_h2(x01), hm01);
                __half2 p23 = __hmul2(ex2_h2(x23), hm23);
                __half2 hp[2] = {p01, p23};
                *(uint2*)&sP[(m*32 + ip)*SP_H + jg*4] = *(uint2*)hp;
            }
        }
        if (jt+1 < 32) { CP_WAIT1; } else { CP_WAIT0; }
        __syncthreads();
        // mma: head am, n-half nh: P[32x32] @ Wh[32x32]; nh==0 warps also P@1 -> den
#pragma unroll
        for (int ks = 0; ks < 2; ks++) {
            uint32_t bfr[2][4];
#pragma unroll
            for (int ntp = 0; ntp < 2; ntp++)
                ldsm_x4t(bfr[ntp], aW[st] + (ks*16*SWH_H + ntp*16)*2);
#pragma unroll
            for (int mt = 0; mt < 2; mt++) {
                uint32_t af[4];
                ldsm_x4(af, aP + (mt*16*SP_H + ks*16)*2);
                if (nh == 0) mma_f16(dacc[mt], af, kONE, kONE);
#pragma unroll
                for (int nt = 0; nt < 4; nt++)
                    mma_f16(acc[mt][nt], af, bfr[nt>>1][(nt&1)*2], bfr[nt>>1][(nt&1)*2+1]);
            }
        }
    }
    // denominator: from dacc fragments (cols identical) -> smem -> reciprocal
    __syncthreads();
    if (nh == 0 && tig == 0) {
#pragma unroll
        for (int mt = 0; mt < 2; mt++) {
            sDen2[am*32 + mt*16 + gid]     = dacc[mt][0];
            sDen2[am*32 + mt*16 + gid + 8] = dacc[mt][2];
        }
    }
    __syncthreads();
    if (t < 128) sDen2[t] = 1.f / fmaxf(sDen2[t], 1e-30f);
    __syncthreads();
    // epilogue: normalize, ELU, store fp16
#pragma unroll
    for (int mt = 0; mt < 2; mt++) {
        int r0 = mt*16 + gid;
        float inv0 = sDen2[am*32 + r0];
        float inv1 = sDen2[am*32 + r0 + 8];
        long row0 = (long)(b*NN) + i0 + r0;
        long row1 = row0 + 8;
#pragma unroll
        for (int nt = 0; nt < 4; nt++) {
            int col = am*192 + e*64 + nh + nt*8 + 2*tig;
            float v0 = acc[mt][nt][0]*inv0, v1 = acc[mt][nt][1]*inv0;
            float v2 = acc[mt][nt][2]*inv1, v3 = acc[mt][nt][3]*inv1;
            v0 = (v0 > 0.f) ? v0 : expm1f(v0);
            v1 = (v1 > 0.f) ? v1 : expm1f(v1);
            v2 = (v2 > 0.f) ? v2 : expm1f(v2);
            v3 = (v3 > 0.f) ? v3 : expm1f(v3);
            *(__half2*)(H + row0*HC + col) = __floats2half2_rn(v0, v1);
            *(__half2*)(H + row1*HC + col) = __floats2half2_rn(v2, v3);
        }
    }
}

// ---------------- batchnorm normalize: fp32 in -> fp16 (+opt fp32) out ----------------
__global__ void norm2_kernel(const float* __restrict__ Y, __half* __restrict__ oh,
                             float* __restrict__ of,
                             const float* __restrict__ stats,
                             const float* __restrict__ g, const float* __restrict__ bb,
                             int N, int elu) {
    int i4 = blockIdx.x*blockDim.x + threadIdx.x;
    if (i4 >= ROWS*N/4) return;
    int i = i4*4;
    int col = i & (N - 1);
    const float invM = 1.f / (float)ROWS;
    float4 y = *(const float4*)(Y + i);
    float4 sm = *(const float4*)(stats + col);
    float4 sq = *(const float4*)(stats + N + col);
    float4 gg = *(const float4*)(g + col);
    float4 bv = *(const float4*)(bb + col);
    float m0 = sm.x*invM, m1 = sm.y*invM, m2 = sm.z*invM, m3 = sm.w*invM;
    float w0 = gg.x * rsqrtf(sq.x*invM - m0*m0 + 1e-5f);
    float w1 = gg.y * rsqrtf(sq.y*invM - m1*m1 + 1e-5f);
    float w2 = gg.z * rsqrtf(sq.z*invM - m2*m2 + 1e-5f);
    float w3 = gg.w * rsqrtf(sq.w*invM - m3*m3 + 1e-5f);
    float v0 = (y.x - m0)*w0 + bv.x;
    float v1 = (y.y - m1)*w1 + bv.y;
    float v2 = (y.z - m2)*w2 + bv.z;
    float v3 = (y.w - m3)*w3 + bv.w;
    if (elu) {
        v0 = (v0 > 0.f) ? v0 : expm1f(v0);
        v1 = (v1 > 0.f) ? v1 : expm1f(v1);
        v2 = (v2 > 0.f) ? v2 : expm1f(v2);
        v3 = (v3 > 0.f) ? v3 : expm1f(v3);
    }
    if (oh) {
        *(__half2*)(oh + i)     = __floats2half2_rn(v0, v1);
        *(__half2*)(oh + i + 2) = __floats2half2_rn(v2, v3);
    }
    if (of) *(float4*)(of + i) = make_float4(v0, v1, v2, v3);
}

// ---------------- launch ----------------
extern "C" void kernel_launch(void* const* d_in, const int* in_sizes, int n_in,
                              void* d_out, int out_size) {
    const int*   A      = (const int*)  d_in[0];
    const float* X      = (const float*)d_in[1];
    const float* Ws     = (const float*)d_in[3];
    const float* a1     = (const float*)d_in[4];
    const float* a2     = (const float*)d_in[5];
    const float* W1     = (const float*)d_in[6];
    const float* bn1_g  = (const float*)d_in[7];
    const float* bn1_b  = (const float*)d_in[8];
    const float* e_l0   = (const float*)d_in[9];
    const float* e_bn0g = (const float*)d_in[10];
    const float* e_bn0b = (const float*)d_in[11];
    const float* e_l1   = (const float*)d_in[12];
    const float* e_bn1g = (const float*)d_in[13];
    const float* e_bn1b = (const float*)d_in[14];
    const float* e_l2   = (const float*)d_in[15];
    const float* bn2_g  = (const float*)d_in[16];
    const float* bn2_b  = (const float*)d_in[17];
    float* out = (float*)d_out;

    float *ps1, *pHnF, *pA, *pSt;
    __half *pXH, *pWtH, *pW1H, *pL0H, *pL1H, *pL2H, *pWh, *pH, *pHnH, *pZ0, *pZ1, *ps2h;
    unsigned short* ppm;
    cudaGetSymbolAddress((void**)&pXH,  d_XH);
    cudaGetSymbolAddress((void**)&pWtH, d_WtH);
    cudaGetSymbolAddress((void**)&pW1H, d_W1H);
    cudaGetSymbolAddress((void**)&pL0H, d_L0H);
    cudaGetSymbolAddress((void**)&pL1H, d_L1H);
    cudaGetSymbolAddress((void**)&pL2H, d_L2H);
    cudaGetSymbolAddress((void**)&pWh,  d_Wh);
    cudaGetSymbolAddress((void**)&pH,   d_H);
    cudaGetSymbolAddress((void**)&pHnH, d_HnH);
    cudaGetSymbolAddress((void**)&pHnF, d_HnF);
    cudaGetSymbolAddress((void**)&pZ0,  d_Z0h);
    cudaGetSymbolAddress((void**)&pZ1,  d_Z1h);
    cudaGetSymbolAddress((void**)&ps1,  d_s1);
    cudaGetSymbolAddress((void**)&ps2h, d_s2h);
    cudaGetSymbolAddress((void**)&ppm,  d_pm);
    cudaGetSymbolAddress((void**)&pA,   d_bufA);
    cudaGetSymbolAddress((void**)&pSt,  d_stats);

    static cudaStream_t s2str = nullptr;
    static cudaEvent_t evFork = nullptr, evJoin = nullptr;
    if (!s2str) {
        cudaStreamCreateWithFlags(&s2str, cudaStreamNonBlocking);
        cudaEventCreateWithFlags(&evFork, cudaEventDisableTiming);
        cudaEventCreateWithFlags(&evJoin, cudaEventDisableTiming);
    }

    // Fork: edge_cat + mask on side stream, overlapping main-stream prologue only
    cudaEventRecord(evFork, 0);
    cudaStreamWaitEvent(s2str, evFork, 0);
    edge2_kernel<<<ROWS, 256, 0, s2str>>>(A, out + ROWS*FF, ppm);
    cudaEventRecord(evJoin, s2str);

    // Main prologue: all conversions + relayout + stats zero in ONE launch
    prep_kernel<<<PREP_BLOCKS, 256>>>(X, W1, e_l0, e_l1, e_l2, Ws, (float4*)pSt);

    // Wh projection + direct s1 (fp32) / s2 (fp16), log2e-scaled
    gemm4_kernel<1><<<dim3(SLOTS/64, NN/64, BE), 256>>>(
        pXH, pWtH, pWh, NN, SLOTS, FF,
        (long)NN*FF, (long)FF*SLOTS, (long)NN*SLOTS, EE, EE,
        1.f, nullptr, 0.f, nullptr, a1, a2, ps1, ps2h);

    cudaStreamWaitEvent(0, evJoin, 0);   // edge drained before att (protect L2 reuse)

    // fused masked softmax + P@Wh + ELU -> H
    att6_kernel<<<dim3(NN/32, BE), 256>>>(ppm, pWh, ps1, ps2h, pH);

    // H @ W1 * 0.5 + 0.5*X -> bufA, stats0; bn1 -> HnH + HnF
    gemm4_kernel<0><<<dim3(FF/64, ROWS/64, 1), 256>>>(
        pH, pW1H, pA, ROWS, FF, HC, 0,0,0, 1,1,
        0.5f, X, 0.5f, pSt + 0, nullptr, nullptr, nullptr, nullptr);
    norm2_kernel<<<(ROWS*FF/4+255)/256, 256>>>(pA, pHnH, pHnF, pSt + 0, bn1_g, bn1_b, FF, 0);

    // Hn @ e_l0 -> bufA, stats1; elu(bn) -> Z0
    gemm4_kernel<0><<<dim3(L0C/64, ROWS/64, 1), 256>>>(
        pHnH, pL0H, pA, ROWS, L0C, FF, 0,0,0, 1,1,
        1.f, nullptr, 0.f, pSt + 512, nullptr, nullptr, nullptr, nullptr);
    norm2_kernel<<<(ROWS*L0C/4+255)/256, 256>>>(pA, pZ0, nullptr, pSt + 512, e_bn0g, e_bn0b, L0C, 1);

    // Z0 @ e_l1 -> bufA, stats2; elu(bn) -> Z1
    gemm4_kernel<0><<<dim3(L1C/64, ROWS/64, 1), 256>>>(
        pZ0, pL1H, pA, ROWS, L1C, L0C, 0,0,0, 1,1,
        1.f, nullptr, 0.f, pSt + 1024, nullptr, nullptr, nullptr, nullptr);
    norm2_kernel<<<(ROWS*L1C/4+255)/256, 256>>>(pA, pZ1, nullptr, pSt + 1024, e_bn1g, e_bn1b, L1C, 1);

    // Z1 @ e_l2 + HnF -> bufA, stats3; bn2 -> out
    gemm4_kernel<0><<<dim3(FF/64, ROWS/64, 1), 256>>>(
        pZ1, pL2H, pA, ROWS, FF, L1C, 0,0,0, 1,1,
        1.f, pHnF, 1.f, pSt + 1536, nullptr, nullptr, nullptr, nullptr);
    norm2_kernel<<<(ROWS*FF/4+255)/256, 256>>>(pA, nullptr, out, pSt + 1536, bn2_g, bn2_b, FF, 0);
}